// round 11
// baseline (speedup 1.0000x reference)
#include <cuda_runtime.h>
#include <cstdint>

// Problem constants (fixed by setup_inputs): B=2, N=256, D=256, H=8, LEN=516
#define B_      2
#define N_      256
#define H_      8
#define ITEMS_  131072
#define LEN_    516
#define EPS_    1e-8f
#define TILE_   64
#define NTILES_ (ITEMS_ / TILE_)   // 2048
#define GRID_   304                // 2 persistent CTAs per SM (all co-resident)

typedef unsigned long long u64;

// ---------------- device-global scratch (no allocation allowed) -------------
__device__ float    g_scores[ITEMS_];
__device__ unsigned g_rowsel[512 * 8];   // per-row selection masks (rewritten)
__device__ unsigned g_c1, g_c2, g_c3;    // rotating grid-sync counters
                                         // (zero-init; self-cleaning rotation)

// dynamic smem per CTA:
//   5 stage buffers [64 items x 16 u128, XOR-swizzled] = 5*16384  (81,920)
//   wbuf 1024 u128                                               (16,384)
//   part [11][4][64] f32  (two-step reduction)                   (11,264)
//   outs 512 f32                                                 ( 2,048)
//   wts  40 f32                                                  (   160)
#define BUFB_       16384
#define SMEM_TOTAL  (5 * BUFB_ + 16384 + 11 * 4 * 64 * 4 + 512 * 4 + 40 * 4)

// ---------------- packed f32x2 helpers (sm_103a) ----------------------------
__device__ __forceinline__ u64 ffma2(u64 a, u64 b, u64 c) {
    u64 d;
    asm("fma.rn.f32x2 %0, %1, %2, %3;" : "=l"(d) : "l"(a), "l"(b), "l"(c));
    return d;
}
__device__ __forceinline__ float hadd2(u64 v) {
    float lo, hi;
    asm("mov.b64 {%0, %1}, %2;" : "=f"(lo), "=f"(hi) : "l"(v));
    return lo + hi;
}

// ============================================================================
// cp.async stage copy: stage s = u128 chunks [s*8, s*8+8) of q and k.
//   Swizzled buffer: chunk c (0..15: c<8 q, else k) of item i stored at
//   u128 position i*16 + (c ^ (i & 15)).
// ============================================================================
__device__ __forceinline__ void docopy(uint32_t dbase, const ulonglong2* __restrict__ sb,
                                       long tile, int s, int item0, int cc, uint32_t dcon)
{
    const ulonglong2* src = sb + (tile * TILE_ + item0) * 64 + s * 8 + cc;
    uint32_t d = dbase + dcon;
#pragma unroll
    for (int j = 0; j < 4; j++) {
        asm volatile("cp.async.cg.shared.global [%0], [%1], 16;" :: "r"(d), "l"(src));
        src += 16 * 64;          // 16 items forward in gmem
        d   += 16 * 16 * 16;     // 16 rows of 16 u128
    }
}

// ============================================================================
// Kernel (single, fused): main loop identical to R8/R10 (~51us, 78% of DRAM
//   bound), followed by a cooperative tail that does exact top-k marking and
//   column zeroing in-kernel (replaces the 9.5us second launch).
// ============================================================================
__global__ __launch_bounds__(256, 2)
void fused_all(const ulonglong2* __restrict__ q2, const ulonglong2* __restrict__ k2,
               const float2* __restrict__ sq2, const float2* __restrict__ sk2,
               const float* __restrict__ roi, const float* __restrict__ W,
               const float* __restrict__ bias, const int* __restrict__ node_num_p,
               float4* __restrict__ out4)
{
    extern __shared__ ulonglong2 smem[];
    __shared__ unsigned s_tail[9];                   // 8 warp-ORs + final mask
    ulonglong2* wbuf = smem + 5 * (BUFB_ / 16);      // 1024 u128 (16KB)
    float* part = (float*)(wbuf + 1024);             // [11][4][64]
    float* outs = part + 11 * 4 * 64;                // 512 floats
    float* wts  = outs + 512;                        // 32 tail + 8 bias

    const int t    = threadIdx.x;
    const int w    = t >> 5;
    const int lane = t & 31;
    const int bid  = blockIdx.x;

    // ---- gather permuted weights from W into smem (wbuf[g*16+h*2+half]) ----
    for (int i = t; i < 1024; i += 256) {
        const int g = i >> 4, h = (i >> 1) & 7, half = i & 1;
        const float4 v = *(const float4*)(W + h * LEN_ + half * 256 + g * 4);
        wbuf[i] = *(const ulonglong2*)&v;
    }
    if (t < 32) wts[t]      = W[(t >> 2) * LEN_ + 512 + (t & 3)];
    if (t < 8)  wts[32 + t] = bias[t];

    // copy geometry (constant per thread)
    const int c     = t & 15;
    const int item0 = t >> 4;                        // 0..15
    const int cc    = c & 7;
    const ulonglong2* sb = (c < 8) ? q2 : k2;
    const uint32_t dcon = (uint32_t)((item0 * 16 + (c ^ item0)) * 16);
    const uint32_t bad0 = (uint32_t)__cvta_generic_to_shared(smem);

    // compute-side swizzle positions (constant per thread)
    const int xa = lane & 15;
    const int pq = w ^ xa;
    const int pk = (8 | w) ^ xa;

    u64 acc[22];

    long cur = bid;
    int  cb  = 0;                                    // consume-buffer ring index

    // prologue: stream stages 0..3 of first tile into buffers 0..3
#pragma unroll
    for (int s = 0; s < 4; s++) {
        if (cur < NTILES_) docopy(bad0 + s * BUFB_, sb, cur, s, item0, cc, dcon);
        asm volatile("cp.async.commit_group;");
    }

    for (; cur < NTILES_; cur += GRID_) {
#pragma unroll
        for (int v = 0; v < 22; v++) acc[v] = 0ull;
        float2 sqa, sqb, ska, skb; float ra, rb;

#pragma unroll
        for (int s = 0; s < 8; s++) {
            asm volatile("cp.async.wait_group 3;");
            __syncthreads();                          // stage s ready & visible

            // refill stage s+4 (this tile if s<4, else next tile s-4)
            {
                int rbuf = cb + 4; if (rbuf >= 5) rbuf -= 5;
                const long rt = (s < 4) ? cur : cur + GRID_;
                const int  rs = (s + 4) & 7;
                if (rt < NTILES_) docopy(bad0 + rbuf * BUFB_, sb, rt, rs, item0, cc, dcon);
                asm volatile("cp.async.commit_group;");
            }
            if (s == 0) {                             // prefetch epilogue operands
                const int ig = (int)cur * TILE_ + lane;
                sqa = sq2[ig];       ska = sk2[ig];       ra = roi[ig];
                sqb = sq2[ig + 32];  skb = sk2[ig + 32];  rb = roi[ig + 32];
            }

            // ---- compute stage s from ring buffer cb ----
            {
                const ulonglong2* bp = smem + cb * (BUFB_ / 16);
                const ulonglong2* da = bp + lane * 16;
                const ulonglong2* db = bp + (lane + 32) * 16;
                const ulonglong2 qa = da[pq], ka = da[pk];
                const ulonglong2 qb = db[pq], kb = db[pk];
                const ulonglong2* wp = wbuf + (s * 8 + w) * 16;
#pragma unroll
                for (int h = 0; h < 8; h++) {
                    const ulonglong2 wq = wp[h * 2];
                    const ulonglong2 wk = wp[h * 2 + 1];
                    acc[h] = ffma2(qa.x, wq.x, acc[h]);
                    acc[h] = ffma2(qa.y, wq.y, acc[h]);
                    acc[h] = ffma2(ka.x, wk.x, acc[h]);
                    acc[h] = ffma2(ka.y, wk.y, acc[h]);
                    acc[11 + h] = ffma2(qb.x, wq.x, acc[11 + h]);
                    acc[11 + h] = ffma2(qb.y, wq.y, acc[11 + h]);
                    acc[11 + h] = ffma2(kb.x, wk.x, acc[11 + h]);
                    acc[11 + h] = ffma2(kb.y, wk.y, acc[11 + h]);
                }
                acc[8]  = ffma2(qa.x, ka.x, acc[8]);  acc[8]  = ffma2(qa.y, ka.y, acc[8]);
                acc[9]  = ffma2(qa.x, qa.x, acc[9]);  acc[9]  = ffma2(qa.y, qa.y, acc[9]);
                acc[10] = ffma2(ka.x, ka.x, acc[10]); acc[10] = ffma2(ka.y, ka.y, acc[10]);
                acc[19] = ffma2(qb.x, kb.x, acc[19]); acc[19] = ffma2(qb.y, kb.y, acc[19]);
                acc[20] = ffma2(qb.x, qb.x, acc[20]); acc[20] = ffma2(qb.y, qb.y, acc[20]);
                acc[21] = ffma2(kb.x, kb.x, acc[21]); acc[21] = ffma2(kb.y, kb.y, acc[21]);
            }
            cb = (cb + 1 == 5) ? 0 : cb + 1;
        }

        // ---- two-step partials: warps 4-7 write, warps 0-3 combine ----
        if (w >= 4) {
#pragma unroll
            for (int v = 0; v < 11; v++) {
                part[(v * 4 + (w - 4)) * 64 + lane]      = hadd2(acc[v]);
                part[(v * 4 + (w - 4)) * 64 + 32 + lane] = hadd2(acc[11 + v]);
            }
        }
        __syncthreads();
        if (w < 4) {
#pragma unroll
            for (int v = 0; v < 11; v++) {
                part[(v * 4 + w) * 64 + lane]      += hadd2(acc[v]);
                part[(v * 4 + w) * 64 + 32 + lane] += hadd2(acc[11 + v]);
            }
        }
        __syncthreads();

        // ---- epilogue: heads (warp w = head w; items lane, lane+32) ----
        {
            float s1 = 0.f, s2 = 0.f;
#pragma unroll
            for (int w2 = 0; w2 < 4; w2++) {
                s1 += part[(w * 4 + w2) * 64 + lane];
                s2 += part[(w * 4 + w2) * 64 + 32 + lane];
            }
            const float4 wt = *(const float4*)(wts + w * 4);
            const float bb = wts[32 + w];
            const float p1 = s1 + sqa.x * wt.x + sqa.y * wt.y
                                + ska.x * wt.z + ska.y * wt.w + bb;
            const float p2 = s2 + sqb.x * wt.x + sqb.y * wt.y
                                + skb.x * wt.z + skb.y * wt.w + bb;
            outs[lane * 8 + w]        = (1.0f / (1.0f + __expf(-p1))) * ra;
            outs[(lane + 32) * 8 + w] = (1.0f / (1.0f + __expf(-p2))) * rb;
        }
        // ---- epilogue: cosine (threads 0..63, item = t) ----
        if (t < 64) {
            float qk = 0.f, qq = 0.f, kk = 0.f;
#pragma unroll
            for (int w2 = 0; w2 < 4; w2++) {
                qk += part[(8  * 4 + w2) * 64 + t];
                qq += part[(9  * 4 + w2) * 64 + t];
                kk += part[(10 * 4 + w2) * 64 + t];
            }
            const float qn = fmaxf(sqrtf(qq), EPS_);
            const float kn = fmaxf(sqrtf(kk), EPS_);
            g_scores[(int)cur * TILE_ + t] = fmaxf(qk / (qn * kn), 0.0f);
        }
        __syncthreads();                              // outs ready
        if (t < 128) out4[cur * 128 + t] = ((const float4*)outs)[t];
    }

    // ========================================================================
    // Cooperative tail (all 304 CTAs co-resident by construction).
    // Counter rotation: sync1's last arriver resets c3; sync2's last resets
    // c1; end's last resets c2 -> all counters zero for the next replay.
    // ========================================================================

    // ---- grid sync 1: all g_scores visible ----
    __threadfence();                                  // release scores/out
    __syncthreads();
    if (t == 0) {
        const unsigned old = atomicAdd(&g_c1, 1u);
        if (old == GRID_ - 1) { g_c3 = 0u; __threadfence(); }
        unsigned v;
        do { asm volatile("ld.global.cv.u32 %0, [%1];" : "=r"(v) : "l"(&g_c1)); }
        while (v < GRID_);
    }
    __syncthreads();

    // ---- phase 2: rows 2*bid, 2*bid+1 (warps 0,1 of CTAs 0..255) ----
    if (bid < 256 && w < 2) {
        const int row = bid * 2 + w;
        const int nn  = *node_num_p;
        const float4* rp = (const float4*)(g_scores + row * N_);
        const float4 v0 = __ldcg(rp + lane * 2);
        const float4 v1 = __ldcg(rp + lane * 2 + 1);
        unsigned key[8];
        key[0] = __float_as_uint(v0.x); key[1] = __float_as_uint(v0.y);
        key[2] = __float_as_uint(v0.z); key[3] = __float_as_uint(v0.w);
        key[4] = __float_as_uint(v1.x); key[5] = __float_as_uint(v1.y);
        key[6] = __float_as_uint(v1.z); key[7] = __float_as_uint(v1.w);

        // radix descend from bit 30 (keys = relu(cosine) >= 0: sign bit 0)
        unsigned prefix = 0, mask = 0;
        int k = nn;
#pragma unroll
        for (int b = 30; b >= 0; b--) {
            const unsigned bit = 1u << b;
            const unsigned m = mask | bit, p = prefix | bit;
            int cl = 0;
#pragma unroll
            for (int i = 0; i < 8; i++) cl += ((key[i] & m) == p);
            const int cnt = __reduce_add_sync(0xffffffffu, cl);
            if (cnt >= k) prefix = p; else k -= cnt;
            mask = m;
        }
        const unsigned T = prefix;
        const int cnt_gt = nn - k;

        int eqc = 0;
#pragma unroll
        for (int i = 0; i < 8; i++) eqc += (key[i] == T);
        int ex = eqc;
#pragma unroll
        for (int o = 1; o < 32; o <<= 1) {
            const int nb = __shfl_up_sync(0xffffffffu, ex, o);
            if (lane >= o) ex += nb;
        }
        ex -= eqc;                                    // exclusive tie prefix

        unsigned bits = 0;
        int run = cnt_gt + ex;
#pragma unroll
        for (int i = 0; i < 8; i++) {
            const bool eq = (key[i] == T);
            if ((key[i] > T) || (eq && run < nn)) bits |= (1u << i);
            run += eq;
        }
        // compact: word j = OR of 8-bit fields of lanes 4j..4j+3
        unsigned field = bits << ((lane & 3) * 8);
        unsigned f1 = field | __shfl_down_sync(0xffffffffu, field, 1);
        unsigned f2 = f1    | __shfl_down_sync(0xffffffffu, f1, 2);
        const unsigned wv = __shfl_sync(0xffffffffu, f2, (lane & 7) * 4);
        if (lane < 8) g_rowsel[row * 8 + lane] = wv;  // exclusive slot
    }

    // ---- grid sync 2: all row masks visible ----
    __threadfence();
    __syncthreads();
    if (t == 0) {
        const unsigned old = atomicAdd(&g_c2, 1u);
        if (old == GRID_ - 1) { g_c1 = 0u; __threadfence(); }
        unsigned v;
        do { asm volatile("ld.global.cv.u32 %0, [%1];" : "=r"(v) : "l"(&g_c2)); }
        while (v < GRID_);
    }
    __syncthreads();

    // ---- phase 3: column bid — OR over 512 rows; zero if unselected ----
    if (bid < 256) {
        const int col  = bid;
        const int word = col >> 5;
        unsigned o = __ldcg(&g_rowsel[t * 8 + word])
                   | __ldcg(&g_rowsel[(t + 256) * 8 + word]);
        o = __reduce_or_sync(0xffffffffu, o);
        if (lane == 0) s_tail[w] = o;
        __syncthreads();
        if (t == 0) {
            unsigned m = 0;
#pragma unroll
            for (int i = 0; i < 8; i++) m |= s_tail[i];
            s_tail[8] = m;
        }
        __syncthreads();
        if (((s_tail[8] >> (col & 31)) & 1u) == 0u) { // unselected: zero column
            const float4 z = make_float4(0.f, 0.f, 0.f, 0.f);
#pragma unroll
            for (int j = 0; j < 2; j++) {
                const int r = t * 2 + j;              // rows 0..511
                const long base = ((long)r * N_ + col) * 2;
                out4[base]     = z;
                out4[base + 1] = z;
            }
        }
    }

    // ---- end: last CTA resets c2 for the next replay ----
    __syncthreads();
    if (t == 0) {
        const unsigned old = atomicAdd(&g_c3, 1u);
        if (old == GRID_ - 1) g_c2 = 0u;
    }
}

// ============================================================================
extern "C" void kernel_launch(void* const* d_in, const int* in_sizes, int n_in,
                              void* d_out, int out_size)
{
    (void)in_sizes; (void)n_in; (void)out_size;
    const ulonglong2* q2  = (const ulonglong2*)d_in[0];
    const ulonglong2* k2  = (const ulonglong2*)d_in[1];
    const float2*     sq  = (const float2*)d_in[2];
    const float2*     sk  = (const float2*)d_in[3];
    const float*      roi = (const float*)d_in[4];
    const float*      W   = (const float*)d_in[5];
    const float*      b   = (const float*)d_in[6];
    const int*        nn  = (const int*)d_in[7];
    float4* out4 = (float4*)d_out;

    cudaFuncSetAttribute(fused_all, cudaFuncAttributeMaxDynamicSharedMemorySize,
                         SMEM_TOTAL);

    fused_all<<<GRID_, 256, SMEM_TOTAL>>>(q2, k2, sq, sk, roi, W, b, nn, out4);
}

// round 12
// speedup vs baseline: 1.0836x; 1.0836x over previous
#include <cuda_runtime.h>
#include <cstdint>

// Problem constants (fixed by setup_inputs): B=2, N=256, D=256, H=8, LEN=516
#define B_      2
#define N_      256
#define H_      8
#define ITEMS_  131072
#define LEN_    516
#define EPS_    1e-8f
#define TILE_   64
#define NTILES_ (ITEMS_ / TILE_)   // 2048
#define GRID_   304                // 2 persistent CTAs per SM
#define MBLK_   64                 // mark_apply blocks (8 rows each)

typedef unsigned long long u64;

// ---------------- device-global scratch (no allocation allowed) -------------
__device__ float    g_scores[ITEMS_];
__device__ unsigned g_partial[MBLK_ * 8];  // per-block votes (fully rewritten)
__device__ unsigned g_done;                // static zero-init; closer resets

// dynamic smem per CTA (identical budget to R8):
//   5 stage buffers [64 items x 16 u128, XOR-swizzled] = 5*16384  (81,920)
//   wbuf 1024 u128                                               (16,384)
//   part [11][4][64] f32  (two-step reduction)                   (11,264)
//   outs 512 f32                                                 ( 2,048)
//   wts  40 f32                                                  (   160)
#define BUFB_       16384
#define SMEM_TOTAL  (5 * BUFB_ + 16384 + 11 * 4 * 64 * 4 + 512 * 4 + 40 * 4)

// ---------------- packed f32x2 helpers (sm_103a) ----------------------------
__device__ __forceinline__ u64 ffma2(u64 a, u64 b, u64 c) {
    u64 d;
    asm("fma.rn.f32x2 %0, %1, %2, %3;" : "=l"(d) : "l"(a), "l"(b), "l"(c));
    return d;
}
__device__ __forceinline__ float hadd2(u64 v) {
    float lo, hi;
    asm("mov.b64 {%0, %1}, %2;" : "=f"(lo), "=f"(hi) : "l"(v));
    return lo + hi;
}

// ============================================================================
// cp.async stage copy: stage s = u128 chunks [s*8, s*8+8) of q and k.
//   Swizzled buffer: chunk c (0..15: c<8 q, else k) of item i stored at
//   u128 position i*16 + (c ^ (i & 15)).
// ============================================================================
__device__ __forceinline__ void docopy(uint32_t dbase, const ulonglong2* __restrict__ sb,
                                       long tile, int s, int item0, int cc, uint32_t dcon)
{
    const ulonglong2* src = sb + (tile * TILE_ + item0) * 64 + s * 8 + cc;
    uint32_t d = dbase + dcon;
#pragma unroll
    for (int j = 0; j < 4; j++) {
        asm volatile("cp.async.cg.shared.global [%0], [%1], 16;" :: "r"(d), "l"(src));
        src += 16 * 64;          // 16 items forward in gmem
        d   += 16 * 16 * 16;     // 16 rows of 16 u128
    }
}

// ============================================================================
// Kernel 1 (fused): 2 CTAs/SM, 256 threads, TILE=64, 8 stages x 32 channels,
//   5-buffer ring, PAIR-BARRIER pipeline: one wait_group+__syncthreads per
//   TWO stages (4 per tile instead of 8). Invariant at each barrier:
//   outstanding groups = {p, p+1, p+2}; wait_group 1 -> p,p+1 complete;
//   refill p+3,p+4 whose buffers held p-2,p-1 (consumed before this barrier).
//   Same 4-stage issue lead as R8.
// ============================================================================
__global__ __launch_bounds__(256, 2)
void fused_main(const ulonglong2* __restrict__ q2, const ulonglong2* __restrict__ k2,
                const float2* __restrict__ sq2, const float2* __restrict__ sk2,
                const float* __restrict__ roi, const float* __restrict__ W,
                const float* __restrict__ bias, float4* __restrict__ out4)
{
    extern __shared__ ulonglong2 smem[];
    ulonglong2* wbuf = smem + 5 * (BUFB_ / 16);      // 1024 u128 (16KB)
    float* part = (float*)(wbuf + 1024);             // [11][4][64]
    float* outs = part + 11 * 4 * 64;                // 512 floats
    float* wts  = outs + 512;                        // 32 tail + 8 bias

    const int t    = threadIdx.x;
    const int w    = t >> 5;
    const int lane = t & 31;

    // ---- gather permuted weights from W into smem (wbuf[g*16+h*2+half]) ----
    for (int i = t; i < 1024; i += 256) {
        const int g = i >> 4, h = (i >> 1) & 7, half = i & 1;
        const float4 v = *(const float4*)(W + h * LEN_ + half * 256 + g * 4);
        wbuf[i] = *(const ulonglong2*)&v;
    }
    if (t < 32) wts[t]      = W[(t >> 2) * LEN_ + 512 + (t & 3)];
    if (t < 8)  wts[32 + t] = bias[t];

    // copy geometry (constant per thread)
    const int c     = t & 15;
    const int item0 = t >> 4;                        // 0..15
    const int cc    = c & 7;
    const ulonglong2* sb = (c < 8) ? q2 : k2;
    const uint32_t dcon = (uint32_t)((item0 * 16 + (c ^ item0)) * 16);
    const uint32_t bad0 = (uint32_t)__cvta_generic_to_shared(smem);

    // compute-side swizzle positions (constant per thread)
    const int xa = lane & 15;
    const int pq = w ^ xa;
    const int pk = (8 | w) ^ xa;

    u64 acc[22];

    auto compute = [&](int s, int cbuf) {
        const ulonglong2* bp = smem + cbuf * (BUFB_ / 16);
        const ulonglong2* da = bp + lane * 16;
        const ulonglong2* db = bp + (lane + 32) * 16;
        const ulonglong2 qa = da[pq], ka = da[pk];
        const ulonglong2 qb = db[pq], kb = db[pk];
        const ulonglong2* wp = wbuf + (s * 8 + w) * 16;
#pragma unroll
        for (int h = 0; h < 8; h++) {
            const ulonglong2 wq = wp[h * 2];
            const ulonglong2 wk = wp[h * 2 + 1];
            acc[h] = ffma2(qa.x, wq.x, acc[h]);
            acc[h] = ffma2(qa.y, wq.y, acc[h]);
            acc[h] = ffma2(ka.x, wk.x, acc[h]);
            acc[h] = ffma2(ka.y, wk.y, acc[h]);
            acc[11 + h] = ffma2(qb.x, wq.x, acc[11 + h]);
            acc[11 + h] = ffma2(qb.y, wq.y, acc[11 + h]);
            acc[11 + h] = ffma2(kb.x, wk.x, acc[11 + h]);
            acc[11 + h] = ffma2(kb.y, wk.y, acc[11 + h]);
        }
        acc[8]  = ffma2(qa.x, ka.x, acc[8]);  acc[8]  = ffma2(qa.y, ka.y, acc[8]);
        acc[9]  = ffma2(qa.x, qa.x, acc[9]);  acc[9]  = ffma2(qa.y, qa.y, acc[9]);
        acc[10] = ffma2(ka.x, ka.x, acc[10]); acc[10] = ffma2(ka.y, ka.y, acc[10]);
        acc[19] = ffma2(qb.x, kb.x, acc[19]); acc[19] = ffma2(qb.y, kb.y, acc[19]);
        acc[20] = ffma2(qb.x, qb.x, acc[20]); acc[20] = ffma2(qb.y, qb.y, acc[20]);
        acc[21] = ffma2(kb.x, kb.x, acc[21]); acc[21] = ffma2(kb.y, kb.y, acc[21]);
    };

    long cur = blockIdx.x;
    int  cb  = 0;                                    // consume-buffer ring index

    // prologue: stream stages 0,1,2 of first tile into buffers 0,1,2
#pragma unroll
    for (int s = 0; s < 3; s++) {
        if (cur < NTILES_) docopy(bad0 + s * BUFB_, sb, cur, s, item0, cc, dcon);
        asm volatile("cp.async.commit_group;");
    }

    for (; cur < NTILES_; cur += GRID_) {
#pragma unroll
        for (int v = 0; v < 22; v++) acc[v] = 0ull;
        float2 sqa, sqb, ska, skb; float ra, rb;

#pragma unroll
        for (int j = 0; j < 4; j++) {
            asm volatile("cp.async.wait_group 1;");
            __syncthreads();                          // stages 2j,2j+1 ready;
                                                      // everyone done with 2j-2,2j-1
            // refill stream stages 2j+3 and 2j+4
            {
                int  rb = cb + 3; if (rb >= 5) rb -= 5;
                int  rs = 2 * j + 3;
                long rt = cur;
                if (rs >= 8) { rs -= 8; rt += GRID_; }
                if (rt < NTILES_) docopy(bad0 + rb * BUFB_, sb, rt, rs, item0, cc, dcon);
                asm volatile("cp.async.commit_group;");

                rb = cb + 4; if (rb >= 5) rb -= 5;
                rs = 2 * j + 4;
                rt = cur;
                if (rs >= 8) { rs -= 8; rt += GRID_; }
                if (rt < NTILES_) docopy(bad0 + rb * BUFB_, sb, rt, rs, item0, cc, dcon);
                asm volatile("cp.async.commit_group;");
            }
            if (j == 0) {                             // prefetch epilogue operands
                const int ig = (int)cur * TILE_ + lane;
                sqa = sq2[ig];       ska = sk2[ig];       ra = roi[ig];
                sqb = sq2[ig + 32];  skb = sk2[ig + 32];  rb = roi[ig + 32];
            }

            compute(2 * j,     cb);  cb = (cb + 1 == 5) ? 0 : cb + 1;
            compute(2 * j + 1, cb);  cb = (cb + 1 == 5) ? 0 : cb + 1;
        }

        // ---- two-step partials: warps 4-7 write, warps 0-3 combine ----
        if (w >= 4) {
#pragma unroll
            for (int v = 0; v < 11; v++) {
                part[(v * 4 + (w - 4)) * 64 + lane]      = hadd2(acc[v]);
                part[(v * 4 + (w - 4)) * 64 + 32 + lane] = hadd2(acc[11 + v]);
            }
        }
        __syncthreads();
        if (w < 4) {
#pragma unroll
            for (int v = 0; v < 11; v++) {
                part[(v * 4 + w) * 64 + lane]      += hadd2(acc[v]);
                part[(v * 4 + w) * 64 + 32 + lane] += hadd2(acc[11 + v]);
            }
        }
        __syncthreads();

        // ---- epilogue: heads (warp w = head w; items lane, lane+32) ----
        {
            float s1 = 0.f, s2 = 0.f;
#pragma unroll
            for (int w2 = 0; w2 < 4; w2++) {
                s1 += part[(w * 4 + w2) * 64 + lane];
                s2 += part[(w * 4 + w2) * 64 + 32 + lane];
            }
            const float4 wt = *(const float4*)(wts + w * 4);
            const float bb = wts[32 + w];
            const float p1 = s1 + sqa.x * wt.x + sqa.y * wt.y
                                + ska.x * wt.z + ska.y * wt.w + bb;
            const float p2 = s2 + sqb.x * wt.x + sqb.y * wt.y
                                + skb.x * wt.z + skb.y * wt.w + bb;
            outs[lane * 8 + w]        = (1.0f / (1.0f + __expf(-p1))) * ra;
            outs[(lane + 32) * 8 + w] = (1.0f / (1.0f + __expf(-p2))) * rb;
        }
        // ---- epilogue: cosine (threads 0..63, item = t) ----
        if (t < 64) {
            float qk = 0.f, qq = 0.f, kk = 0.f;
#pragma unroll
            for (int w2 = 0; w2 < 4; w2++) {
                qk += part[(8  * 4 + w2) * 64 + t];
                qq += part[(9  * 4 + w2) * 64 + t];
                kk += part[(10 * 4 + w2) * 64 + t];
            }
            const float qn = fmaxf(sqrtf(qq), EPS_);
            const float kn = fmaxf(sqrtf(kk), EPS_);
            g_scores[(int)cur * TILE_ + t] = fmaxf(qk / (qn * kn), 0.0f);
        }
        __syncthreads();                              // outs ready
        if (t < 128) out4[cur * 128 + t] = ((const float4*)outs)[t];
    }
}

// ============================================================================
// Kernel 2: 64 blocks x 256 threads (8 warps = 8 rows/block).
//   Per-row exact top-k via radix select; block ORs warp votes in smem and
//   plain-stores its 8-word mask to a private g_partial slot (no contended
//   atomics). Last block OR-reduces the 64 slots, zeroes unselected columns,
//   resets g_done. Exact jax.lax.top_k semantics:
//   selected(t) iff key>T, or key==T and cnt_gt + #{j<t ties} < nn.
// ============================================================================
__global__ __launch_bounds__(256, 4)
void mark_apply(const int* __restrict__ node_num_p, float4* __restrict__ out4)
{
    __shared__ unsigned smask[8];
    __shared__ unsigned s_last;

    const int t = threadIdx.x;
    if (t < 8) smask[t] = 0u;
    __syncthreads();

    const int row  = blockIdx.x * 8 + (t >> 5);       // 0..511
    const int lane = t & 31;
    const int nn   = *node_num_p;

    const float4* rp = (const float4*)(g_scores + row * N_);
    const float4 v0 = rp[lane * 2];
    const float4 v1 = rp[lane * 2 + 1];
    unsigned key[8];
    key[0] = __float_as_uint(v0.x); key[1] = __float_as_uint(v0.y);
    key[2] = __float_as_uint(v0.z); key[3] = __float_as_uint(v0.w);
    key[4] = __float_as_uint(v1.x); key[5] = __float_as_uint(v1.y);
    key[6] = __float_as_uint(v1.z); key[7] = __float_as_uint(v1.w);

    // radix descend from bit 30 (keys = relu(cosine) in [0,1]: sign bit 0)
    unsigned prefix = 0, mask = 0;
    int k = nn;
#pragma unroll
    for (int b = 30; b >= 0; b--) {
        const unsigned bit = 1u << b;
        const unsigned m = mask | bit, p = prefix | bit;
        int cl = 0;
#pragma unroll
        for (int i = 0; i < 8; i++) cl += ((key[i] & m) == p);
        const int cnt = __reduce_add_sync(0xffffffffu, cl);
        if (cnt >= k) prefix = p; else k -= cnt;
        mask = m;
    }
    const unsigned T = prefix;
    const int cnt_gt = nn - k;

    int eqc = 0;
#pragma unroll
    for (int i = 0; i < 8; i++) eqc += (key[i] == T);
    int ex = eqc;
#pragma unroll
    for (int o = 1; o < 32; o <<= 1) {
        const int nb = __shfl_up_sync(0xffffffffu, ex, o);
        if (lane >= o) ex += nb;
    }
    ex -= eqc;                                        // exclusive tie prefix

    unsigned bits = 0;
    int run = cnt_gt + ex;
#pragma unroll
    for (int i = 0; i < 8; i++) {
        const bool eq = (key[i] == T);
        if ((key[i] > T) || (eq && run < nn)) bits |= (1u << i);
        run += eq;
    }

    // compact: word (lane>>2) gets 8-bit fields of 4 lanes -> 8 smem atomics/warp
    unsigned field = bits << ((lane & 3) * 8);
    unsigned f1 = field | __shfl_down_sync(0xffffffffu, field, 1);
    unsigned f2 = f1    | __shfl_down_sync(0xffffffffu, f1, 2);
    const unsigned wv = __shfl_sync(0xffffffffu, f2, (lane & 7) * 4);
    if (lane < 8 && wv) atomicOr(&smask[lane], wv);
    __syncthreads();

    // publish this block's 8-word mask (plain stores, private slot)
    if (t < 8) g_partial[blockIdx.x * 8 + t] = smask[t];
    __threadfence();                                  // release
    __syncthreads();

    // ---- last-block-closes ----
    if (t == 0)
        s_last = (atomicAdd(&g_done, 1u) == gridDim.x - 1) ? 1u : 0u;
    __syncthreads();
    if (s_last) {
        __threadfence();                              // acquire all partials
        // OR-reduce: thread t owns word (t&7), scans blocks (t>>3)+32j
        unsigned acc = 0;
        for (int blk = (t >> 3); blk < MBLK_; blk += 32)
            acc |= g_partial[blk * 8 + (t & 7)];
        if (t < 8) smask[t] = 0u;
        __syncthreads();
        atomicOr(&smask[t & 7], acc);
        __syncthreads();

        // zero unselected columns (1 column per thread)
        {
            const int col = t;
            const unsigned m = smask[col >> 5];
            if (((m >> (col & 31)) & 1u) == 0u) {
                const float4 z = make_float4(0.f, 0.f, 0.f, 0.f);
                for (int r = 0; r < 512; r++) {
                    const long base = ((long)r * N_ + col) * 2;
                    out4[base]     = z;
                    out4[base + 1] = z;
                }
            }
        }
        __syncthreads();
        if (t == 0) g_done = 0u;                      // reset for next replay
    }
}

// ============================================================================
extern "C" void kernel_launch(void* const* d_in, const int* in_sizes, int n_in,
                              void* d_out, int out_size)
{
    (void)in_sizes; (void)n_in; (void)out_size;
    const ulonglong2* q2  = (const ulonglong2*)d_in[0];
    const ulonglong2* k2  = (const ulonglong2*)d_in[1];
    const float2*     sq  = (const float2*)d_in[2];
    const float2*     sk  = (const float2*)d_in[3];
    const float*      roi = (const float*)d_in[4];
    const float*      W   = (const float*)d_in[5];
    const float*      b   = (const float*)d_in[6];
    const int*        nn  = (const int*)d_in[7];
    float4* out4 = (float4*)d_out;

    cudaFuncSetAttribute(fused_main, cudaFuncAttributeMaxDynamicSharedMemorySize,
                         SMEM_TOTAL);

    fused_main<<<GRID_, 256, SMEM_TOTAL>>>(q2, k2, sq, sk, roi, W, b, out4);
    mark_apply<<<MBLK_, 256>>>(nn, out4);
}

// round 13
// speedup vs baseline: 1.0958x; 1.0113x over previous
#include <cuda_runtime.h>
#include <cstdint>

// Problem constants (fixed by setup_inputs): B=2, N=256, D=256, H=8, LEN=516
#define B_      2
#define N_      256
#define H_      8
#define ITEMS_  131072
#define LEN_    516
#define EPS_    1e-8f
#define TILE_   64
#define NTILES_ (ITEMS_ / TILE_)   // 2048
#define GRID_   304                // 2 persistent CTAs per SM
#define MBLK_   64                 // mark_apply blocks (8 rows each)

typedef unsigned long long u64;

// ---------------- device-global scratch (no allocation allowed) -------------
__device__ float    g_scores[ITEMS_];
__device__ unsigned g_partial[MBLK_ * 8];  // per-block votes (fully rewritten)
__device__ unsigned g_done;                // static zero-init; closer resets

// dynamic smem per CTA (identical budget to R8):
//   5 stage buffers [64 items x 16 u128, XOR-swizzled] = 5*16384  (81,920)
//   wbuf 1024 u128                                               (16,384)
//   part [11][4][64] f32  (two-step reduction)                   (11,264)
//   outs 512 f32                                                 ( 2,048)
//   wts  40 f32                                                  (   160)
#define BUFB_       16384
#define SMEM_TOTAL  (5 * BUFB_ + 16384 + 11 * 4 * 64 * 4 + 512 * 4 + 40 * 4)

// ---------------- packed f32x2 helpers (sm_103a) ----------------------------
__device__ __forceinline__ u64 ffma2(u64 a, u64 b, u64 c) {
    u64 d;
    asm("fma.rn.f32x2 %0, %1, %2, %3;" : "=l"(d) : "l"(a), "l"(b), "l"(c));
    return d;
}
__device__ __forceinline__ float hadd2(u64 v) {
    float lo, hi;
    asm("mov.b64 {%0, %1}, %2;" : "=f"(lo), "=f"(hi) : "l"(v));
    return lo + hi;
}

// ============================================================================
// cp.async stage copy: stage s = u128 chunks [s*8, s*8+8) of q and k.
//   Swizzled buffer: chunk c (0..15: c<8 q, else k) of item i stored at
//   u128 position i*16 + (c ^ (i & 15)).
// ============================================================================
__device__ __forceinline__ void docopy(uint32_t dbase, const ulonglong2* __restrict__ sb,
                                       long tile, int s, int item0, int cc, uint32_t dcon)
{
    const ulonglong2* src = sb + (tile * TILE_ + item0) * 64 + s * 8 + cc;
    uint32_t d = dbase + dcon;
#pragma unroll
    for (int j = 0; j < 4; j++) {
        asm volatile("cp.async.cg.shared.global [%0], [%1], 16;" :: "r"(d), "l"(src));
        src += 16 * 64;          // 16 items forward in gmem
        d   += 16 * 16 * 16;     // 16 rows of 16 u128
    }
}

// ============================================================================
// Kernel 1 (fused): byte-identical main loop to R8 (best measured: ~51us,
//   2 CTAs/SM, TILE=64, 8 stages, ring-5, lookahead-4, one barrier/stage),
//   plus a PDL trigger after the loop so kernel 2's launch overlaps the tail.
// ============================================================================
__global__ __launch_bounds__(256, 2)
void fused_main(const ulonglong2* __restrict__ q2, const ulonglong2* __restrict__ k2,
                const float2* __restrict__ sq2, const float2* __restrict__ sk2,
                const float* __restrict__ roi, const float* __restrict__ W,
                const float* __restrict__ bias, float4* __restrict__ out4)
{
    extern __shared__ ulonglong2 smem[];
    ulonglong2* wbuf = smem + 5 * (BUFB_ / 16);      // 1024 u128 (16KB)
    float* part = (float*)(wbuf + 1024);             // [11][4][64]
    float* outs = part + 11 * 4 * 64;                // 512 floats
    float* wts  = outs + 512;                        // 32 tail + 8 bias

    const int t    = threadIdx.x;
    const int w    = t >> 5;
    const int lane = t & 31;

    // ---- gather permuted weights from W into smem (wbuf[g*16+h*2+half]) ----
    for (int i = t; i < 1024; i += 256) {
        const int g = i >> 4, h = (i >> 1) & 7, half = i & 1;
        const float4 v = *(const float4*)(W + h * LEN_ + half * 256 + g * 4);
        wbuf[i] = *(const ulonglong2*)&v;
    }
    if (t < 32) wts[t]      = W[(t >> 2) * LEN_ + 512 + (t & 3)];
    if (t < 8)  wts[32 + t] = bias[t];

    // copy geometry (constant per thread)
    const int c     = t & 15;
    const int item0 = t >> 4;                        // 0..15
    const int cc    = c & 7;
    const ulonglong2* sb = (c < 8) ? q2 : k2;
    const uint32_t dcon = (uint32_t)((item0 * 16 + (c ^ item0)) * 16);
    const uint32_t bad0 = (uint32_t)__cvta_generic_to_shared(smem);

    // compute-side swizzle positions (constant per thread)
    const int xa = lane & 15;
    const int pq = w ^ xa;
    const int pk = (8 | w) ^ xa;

    u64 acc[22];

    long cur = blockIdx.x;
    int  cb  = 0;                                    // consume-buffer ring index

    // prologue: stream stages 0..3 of first tile into buffers 0..3
#pragma unroll
    for (int s = 0; s < 4; s++) {
        if (cur < NTILES_) docopy(bad0 + s * BUFB_, sb, cur, s, item0, cc, dcon);
        asm volatile("cp.async.commit_group;");
    }

    for (; cur < NTILES_; cur += GRID_) {
#pragma unroll
        for (int v = 0; v < 22; v++) acc[v] = 0ull;
        float2 sqa, sqb, ska, skb; float ra, rb;

#pragma unroll
        for (int s = 0; s < 8; s++) {
            asm volatile("cp.async.wait_group 3;");
            __syncthreads();                          // stage s ready & visible

            // refill stage s+4 (this tile if s<4, else next tile s-4)
            {
                int rbuf = cb + 4; if (rbuf >= 5) rbuf -= 5;
                const long rt = (s < 4) ? cur : cur + GRID_;
                const int  rs = (s + 4) & 7;
                if (rt < NTILES_) docopy(bad0 + rbuf * BUFB_, sb, rt, rs, item0, cc, dcon);
                asm volatile("cp.async.commit_group;");
            }
            if (s == 0) {                             // prefetch epilogue operands
                const int ig = (int)cur * TILE_ + lane;
                sqa = sq2[ig];       ska = sk2[ig];       ra = roi[ig];
                sqb = sq2[ig + 32];  skb = sk2[ig + 32];  rb = roi[ig + 32];
            }

            // ---- compute stage s from ring buffer cb ----
            {
                const ulonglong2* bp = smem + cb * (BUFB_ / 16);
                const ulonglong2* da = bp + lane * 16;
                const ulonglong2* db = bp + (lane + 32) * 16;
                const ulonglong2 qa = da[pq], ka = da[pk];
                const ulonglong2 qb = db[pq], kb = db[pk];
                const ulonglong2* wp = wbuf + (s * 8 + w) * 16;
#pragma unroll
                for (int h = 0; h < 8; h++) {
                    const ulonglong2 wq = wp[h * 2];
                    const ulonglong2 wk = wp[h * 2 + 1];
                    acc[h] = ffma2(qa.x, wq.x, acc[h]);
                    acc[h] = ffma2(qa.y, wq.y, acc[h]);
                    acc[h] = ffma2(ka.x, wk.x, acc[h]);
                    acc[h] = ffma2(ka.y, wk.y, acc[h]);
                    acc[11 + h] = ffma2(qb.x, wq.x, acc[11 + h]);
                    acc[11 + h] = ffma2(qb.y, wq.y, acc[11 + h]);
                    acc[11 + h] = ffma2(kb.x, wk.x, acc[11 + h]);
                    acc[11 + h] = ffma2(kb.y, wk.y, acc[11 + h]);
                }
                acc[8]  = ffma2(qa.x, ka.x, acc[8]);  acc[8]  = ffma2(qa.y, ka.y, acc[8]);
                acc[9]  = ffma2(qa.x, qa.x, acc[9]);  acc[9]  = ffma2(qa.y, qa.y, acc[9]);
                acc[10] = ffma2(ka.x, ka.x, acc[10]); acc[10] = ffma2(ka.y, ka.y, acc[10]);
                acc[19] = ffma2(qb.x, kb.x, acc[19]); acc[19] = ffma2(qb.y, kb.y, acc[19]);
                acc[20] = ffma2(qb.x, qb.x, acc[20]); acc[20] = ffma2(qb.y, qb.y, acc[20]);
                acc[21] = ffma2(kb.x, kb.x, acc[21]); acc[21] = ffma2(kb.y, kb.y, acc[21]);
            }
            cb = (cb + 1 == 5) ? 0 : cb + 1;
        }

        // ---- two-step partials: warps 4-7 write, warps 0-3 combine ----
        if (w >= 4) {
#pragma unroll
            for (int v = 0; v < 11; v++) {
                part[(v * 4 + (w - 4)) * 64 + lane]      = hadd2(acc[v]);
                part[(v * 4 + (w - 4)) * 64 + 32 + lane] = hadd2(acc[11 + v]);
            }
        }
        __syncthreads();
        if (w < 4) {
#pragma unroll
            for (int v = 0; v < 11; v++) {
                part[(v * 4 + w) * 64 + lane]      += hadd2(acc[v]);
                part[(v * 4 + w) * 64 + 32 + lane] += hadd2(acc[11 + v]);
            }
        }
        __syncthreads();

        // ---- epilogue: heads (warp w = head w; items lane, lane+32) ----
        {
            float s1 = 0.f, s2 = 0.f;
#pragma unroll
            for (int w2 = 0; w2 < 4; w2++) {
                s1 += part[(w * 4 + w2) * 64 + lane];
                s2 += part[(w * 4 + w2) * 64 + 32 + lane];
            }
            const float4 wt = *(const float4*)(wts + w * 4);
            const float bb = wts[32 + w];
            const float p1 = s1 + sqa.x * wt.x + sqa.y * wt.y
                                + ska.x * wt.z + ska.y * wt.w + bb;
            const float p2 = s2 + sqb.x * wt.x + sqb.y * wt.y
                                + skb.x * wt.z + skb.y * wt.w + bb;
            outs[lane * 8 + w]        = (1.0f / (1.0f + __expf(-p1))) * ra;
            outs[(lane + 32) * 8 + w] = (1.0f / (1.0f + __expf(-p2))) * rb;
        }
        // ---- epilogue: cosine (threads 0..63, item = t) ----
        if (t < 64) {
            float qk = 0.f, qq = 0.f, kk = 0.f;
#pragma unroll
            for (int w2 = 0; w2 < 4; w2++) {
                qk += part[(8  * 4 + w2) * 64 + t];
                qq += part[(9  * 4 + w2) * 64 + t];
                kk += part[(10 * 4 + w2) * 64 + t];
            }
            const float qn = fmaxf(sqrtf(qq), EPS_);
            const float kn = fmaxf(sqrtf(kk), EPS_);
            g_scores[(int)cur * TILE_ + t] = fmaxf(qk / (qn * kn), 0.0f);
        }
        __syncthreads();                              // outs ready
        if (t < 128) out4[cur * 128 + t] = ((const float4*)outs)[t];
    }

    // PDL: this CTA is done — let the dependent kernel start launching.
    cudaTriggerProgrammaticLaunchCompletion();
}

// ============================================================================
// Kernel 2 (PDL-launched): prologue (smask init, nn load) overlaps kernel 1's
//   tail; cudaGridDependencySynchronize() guarantees kernel-1 completion and
//   memory visibility before g_scores/out4 are touched.
//   Per-row exact top-k via radix select (jax.lax.top_k semantics), block ORs
//   warp votes in smem, plain-stores to a private g_partial slot; last block
//   OR-reduces 64 slots, zeroes unselected columns, resets g_done.
// ============================================================================
__global__ __launch_bounds__(256, 4)
void mark_apply(const int* __restrict__ node_num_p, float4* __restrict__ out4)
{
    __shared__ unsigned smask[8];
    __shared__ unsigned s_last;

    const int t = threadIdx.x;
    if (t < 8) smask[t] = 0u;

    const int row  = blockIdx.x * 8 + (t >> 5);       // 0..511
    const int lane = t & 31;
    const int nn   = *node_num_p;                     // harness input: pre-launch data

    // wait for fused_main to fully complete (memory visible)
    cudaGridDependencySynchronize();
    __syncthreads();                                  // smask init also done

    const float4* rp = (const float4*)(g_scores + row * N_);
    const float4 v0 = rp[lane * 2];
    const float4 v1 = rp[lane * 2 + 1];
    unsigned key[8];
    key[0] = __float_as_uint(v0.x); key[1] = __float_as_uint(v0.y);
    key[2] = __float_as_uint(v0.z); key[3] = __float_as_uint(v0.w);
    key[4] = __float_as_uint(v1.x); key[5] = __float_as_uint(v1.y);
    key[6] = __float_as_uint(v1.z); key[7] = __float_as_uint(v1.w);

    // radix descend from bit 30 (keys = relu(cosine) in [0,1]: sign bit 0)
    unsigned prefix = 0, mask = 0;
    int k = nn;
#pragma unroll
    for (int b = 30; b >= 0; b--) {
        const unsigned bit = 1u << b;
        const unsigned m = mask | bit, p = prefix | bit;
        int cl = 0;
#pragma unroll
        for (int i = 0; i < 8; i++) cl += ((key[i] & m) == p);
        const int cnt = __reduce_add_sync(0xffffffffu, cl);
        if (cnt >= k) prefix = p; else k -= cnt;
        mask = m;
    }
    const unsigned T = prefix;
    const int cnt_gt = nn - k;

    int eqc = 0;
#pragma unroll
    for (int i = 0; i < 8; i++) eqc += (key[i] == T);
    int ex = eqc;
#pragma unroll
    for (int o = 1; o < 32; o <<= 1) {
        const int nb = __shfl_up_sync(0xffffffffu, ex, o);
        if (lane >= o) ex += nb;
    }
    ex -= eqc;                                        // exclusive tie prefix

    unsigned bits = 0;
    int run = cnt_gt + ex;
#pragma unroll
    for (int i = 0; i < 8; i++) {
        const bool eq = (key[i] == T);
        if ((key[i] > T) || (eq && run < nn)) bits |= (1u << i);
        run += eq;
    }

    // compact: word (lane>>2) gets 8-bit fields of 4 lanes -> 8 smem atomics/warp
    unsigned field = bits << ((lane & 3) * 8);
    unsigned f1 = field | __shfl_down_sync(0xffffffffu, field, 1);
    unsigned f2 = f1    | __shfl_down_sync(0xffffffffu, f1, 2);
    const unsigned wv = __shfl_sync(0xffffffffu, f2, (lane & 7) * 4);
    if (lane < 8 && wv) atomicOr(&smask[lane], wv);
    __syncthreads();

    // publish this block's 8-word mask (plain stores, private slot)
    if (t < 8) g_partial[blockIdx.x * 8 + t] = smask[t];
    __threadfence();                                  // release
    __syncthreads();

    // ---- last-block-closes ----
    if (t == 0)
        s_last = (atomicAdd(&g_done, 1u) == gridDim.x - 1) ? 1u : 0u;
    __syncthreads();
    if (s_last) {
        __threadfence();                              // acquire all partials
        // OR-reduce: thread t owns word (t&7), scans blocks (t>>3)+32j
        unsigned acc = 0;
        for (int blk = (t >> 3); blk < MBLK_; blk += 32)
            acc |= g_partial[blk * 8 + (t & 7)];
        if (t < 8) smask[t] = 0u;
        __syncthreads();
        atomicOr(&smask[t & 7], acc);
        __syncthreads();

        // zero unselected columns (1 column per thread)
        {
            const int col = t;
            const unsigned m = smask[col >> 5];
            if (((m >> (col & 31)) & 1u) == 0u) {
                const float4 z = make_float4(0.f, 0.f, 0.f, 0.f);
                for (int r = 0; r < 512; r++) {
                    const long base = ((long)r * N_ + col) * 2;
                    out4[base]     = z;
                    out4[base + 1] = z;
                }
            }
        }
        __syncthreads();
        if (t == 0) g_done = 0u;                      // reset for next replay
    }
}

// ============================================================================
extern "C" void kernel_launch(void* const* d_in, const int* in_sizes, int n_in,
                              void* d_out, int out_size)
{
    (void)in_sizes; (void)n_in; (void)out_size;
    const ulonglong2* q2  = (const ulonglong2*)d_in[0];
    const ulonglong2* k2  = (const ulonglong2*)d_in[1];
    const float2*     sq  = (const float2*)d_in[2];
    const float2*     sk  = (const float2*)d_in[3];
    const float*      roi = (const float*)d_in[4];
    const float*      W   = (const float*)d_in[5];
    const float*      b   = (const float*)d_in[6];
    const int*        nn  = (const int*)d_in[7];
    float4* out4 = (float4*)d_out;

    cudaFuncSetAttribute(fused_main, cudaFuncAttributeMaxDynamicSharedMemorySize,
                         SMEM_TOTAL);

    fused_main<<<GRID_, 256, SMEM_TOTAL>>>(q2, k2, sq, sk, roi, W, b, out4);

    // PDL launch: mark_apply's setup overlaps fused_main's tail.
    cudaLaunchConfig_t cfg = {};
    cfg.gridDim  = dim3(MBLK_, 1, 1);
    cfg.blockDim = dim3(256, 1, 1);
    cfg.dynamicSmemBytes = 0;
    cfg.stream = 0;                                   // same (captured) stream
    cudaLaunchAttribute attrs[1];
    attrs[0].id = cudaLaunchAttributeProgrammaticStreamSerialization;
    attrs[0].val.programmaticStreamSerializationAllowed = 1;
    cfg.attrs = attrs;
    cfg.numAttrs = 1;
    cudaLaunchKernelEx(&cfg, mark_apply, nn, out4);
}